// round 1
// baseline (speedup 1.0000x reference)
#include <cuda_runtime.h>

#define THETA 0.5f
#define CS 128           // rows per chunk

// Scratch (no allocation allowed): per-chunk local endpoints + ready flags.
// Max: B*chunks*D = 64*32*256 = 524288 floats; flags = 2048.
__device__ float g_L[1 << 21];
__device__ int   g_flag[16384];

__global__ void init_flags_kernel(int n) {
    int i = blockIdx.x * blockDim.x + threadIdx.x;
    if (i < n) g_flag[i] = 0;
}

__global__ void ou_scan_kernel(const float* __restrict__ t,
                               const float* __restrict__ x0,
                               const float* __restrict__ z,
                               float* __restrict__ out,
                               int B, int S, int D, int chunks)
{
    extern __shared__ float sm[];
    float* s_c   = sm;            // [CS] decay per row
    float* s_r   = sm + CS;       // [CS] noise scale per row
    float* s_e   = sm + 2 * CS;   // [CS] carry weight per row
    float* s_buf = sm + 3 * CS;   // [CS * D] local scan results

    const int b  = blockIdx.x / chunks;
    const int k  = blockIdx.x % chunks;
    const int s0 = k * CS;
    const int rows = min(CS, S - s0);
    const int d  = threadIdx.x;   // blockDim.x == D

    const float* tb = t + (size_t)b * S;
    const float Tprev = (k == 0) ? 0.0f : tb[s0 - 1];

    // ---- phase 0: per-row constants (c, r, carry weight) ----
    if (d < rows) {
        float tc = tb[s0 + d];
        float tp = (s0 + d == 0) ? 0.0f : tb[s0 + d - 1];
        float c  = expf(-THETA * (tc - tp));
        s_c[d] = c;
        s_r[d] = sqrtf(fmaxf(1.0f - c * c, 0.0f));
        s_e[d] = expf(-THETA * (tc - Tprev));
    }
    __syncthreads();

    // ---- phase 1: local scan (zero carry-in; x0 folded into chunk 0) ----
    const float* zb = z + ((size_t)b * S + s0) * D + d;
    float x = (k == 0) ? x0[(size_t)b * D + d] : 0.0f;
    #pragma unroll 4
    for (int s = 0; s < rows; ++s) {
        float zv = __ldcs(zb + (size_t)s * D);    // streaming: no reuse
        x = fmaf(s_c[s], x, s_r[s] * zv);
        s_buf[s * D + d] = x;
    }

    // ---- publish local endpoint, then release flag ----
    const int cid = b * chunks + k;
    g_L[(size_t)cid * D + d] = x;
    __threadfence();
    __syncthreads();
    if (d == 0) {
        asm volatile("st.release.gpu.global.b32 [%0], %1;"
                     :: "l"(&g_flag[cid]), "r"(1) : "memory");
    }

    // ---- phase 2: closed-form carry from all predecessor chunks ----
    float carry = 0.0f;
    for (int j = 0; j < k; ++j) {
        const int pid = b * chunks + j;
        int f;
        do {
            asm volatile("ld.acquire.gpu.global.b32 %0, [%1];"
                         : "=r"(f) : "l"(&g_flag[pid]) : "memory");
            if (!f) __nanosleep(64);
        } while (!f);
        float Tj = tb[(j + 1) * CS - 1];
        float w  = expf(-THETA * (Tprev - Tj));   // exponent <= 0: stable
        carry = fmaf(w, g_L[(size_t)pid * D + d], carry);
    }

    // ---- phase 3: apply carry, stream results out ----
    float* ob = out + ((size_t)b * S + s0) * D + d;
    #pragma unroll 4
    for (int s = 0; s < rows; ++s) {
        float v = fmaf(s_e[s], carry, s_buf[s * D + d]);
        __stcs(ob + (size_t)s * D, v);
    }
}

extern "C" void kernel_launch(void* const* d_in, const int* in_sizes, int n_in,
                              void* d_out, int out_size)
{
    const float* t  = (const float*)d_in[0];   // [B,S,1]
    const float* x0 = (const float*)d_in[1];   // [B,1,D]
    const float* z  = (const float*)d_in[2];   // [B,S,D]
    float* out = (float*)d_out;                // [B,S,D]

    const long n_t  = in_sizes[0];
    const long n_x0 = in_sizes[1];
    const long n_z  = in_sizes[2];
    const int D = (int)(n_z / n_t);
    const int B = (int)(n_x0 / D);
    const int S = (int)(n_t / B);
    const int chunks = (S + CS - 1) / CS;

    const int nflags = B * chunks;
    init_flags_kernel<<<(nflags + 255) / 256, 256>>>(nflags);

    const size_t smem = (size_t)(3 * CS + CS * D) * sizeof(float);
    cudaFuncSetAttribute(ou_scan_kernel,
                         cudaFuncAttributeMaxDynamicSharedMemorySize, (int)smem);
    ou_scan_kernel<<<B * chunks, D, smem>>>(t, x0, z, out, B, S, D, chunks);
}

// round 2
// speedup vs baseline: 4.1545x; 4.1545x over previous
#include <cuda_runtime.h>

#define THETA 0.5f
#define CS 64            // rows per chunk
#define PF 8             // prefetch depth (rows per pipeline stage)

// Scratch (no allocation allowed): per-chunk local endpoints + ready flags.
// Max: B*chunks*D = 64*64*256 = 1,048,576 floats; flags = 4096.
__device__ float g_L[1 << 21];
__device__ int   g_flag[16384];

__global__ void init_flags_kernel(int n) {
    int i = blockIdx.x * blockDim.x + threadIdx.x;
    if (i < n) g_flag[i] = 0;
}

__global__ __launch_bounds__(256, 3)
void ou_scan_kernel(const float* __restrict__ t,
                    const float* __restrict__ x0,
                    const float* __restrict__ z,
                    float* __restrict__ out,
                    int B, int S, int D, int chunks)
{
    extern __shared__ float sm[];
    float* s_c   = sm;                 // [CS] decay per row
    float* s_r   = sm + CS;            // [CS] noise scale per row
    float* s_e   = sm + 2 * CS;        // [CS] carry weight per row
    float* s_T   = sm + 3 * CS;        // [chunks] predecessor end-times
    float* s_buf = sm + 3 * CS + chunks; // [CS * D] local scan results

    const int b  = blockIdx.x / chunks;
    const int k  = blockIdx.x % chunks;
    const int s0 = k * CS;
    const int rows = min(CS, S - s0);
    const int d  = threadIdx.x;        // blockDim.x == D == 256

    const float* tb = t + (size_t)b * S;
    const float Tprev = (k == 0) ? 0.0f : tb[s0 - 1];

    // ---- phase 0: per-row constants (c, r, carry weight) ----
    if (d < rows) {
        float tc = tb[s0 + d];
        float tp = (s0 + d == 0) ? 0.0f : tb[s0 + d - 1];
        float c  = __expf(-THETA * (tc - tp));
        s_c[d] = c;
        s_r[d] = sqrtf(fmaxf(1.0f - c * c, 0.0f));
        s_e[d] = __expf(-THETA * (tc - Tprev));
    }
    __syncthreads();

    // ---- phase 1: local scan, depth-2 software pipeline (PF rows/stage) ----
    const float* zb = z + ((size_t)b * S + s0) * D + d;
    float x = (k == 0) ? x0[(size_t)b * D + d] : 0.0f;

    float cur[PF], nxt[PF];
    int s = 0;
    if (rows >= PF) {
        #pragma unroll
        for (int u = 0; u < PF; ++u) cur[u] = __ldcs(zb + (size_t)u * D);
    }
    for (s = 0; s + PF <= rows; s += PF) {
        const bool more = (s + 2 * PF <= rows);
        if (more) {
            #pragma unroll
            for (int u = 0; u < PF; ++u)
                nxt[u] = __ldcs(zb + (size_t)(s + PF + u) * D);
        }
        #pragma unroll
        for (int u = 0; u < PF; ++u) {
            x = fmaf(s_c[s + u], x, s_r[s + u] * cur[u]);
            s_buf[(s + u) * D + d] = x;
        }
        #pragma unroll
        for (int u = 0; u < PF; ++u) cur[u] = nxt[u];
    }
    for (; s < rows; ++s) {
        float zv = __ldcs(zb + (size_t)s * D);
        x = fmaf(s_c[s], x, s_r[s] * zv);
        s_buf[s * D + d] = x;
    }

    // ---- publish local endpoint, then release flag ----
    const int base = b * chunks;
    const int cid  = base + k;
    g_L[(size_t)cid * D + d] = x;
    __threadfence();
    __syncthreads();
    if (d == 0) {
        asm volatile("st.release.gpu.global.b32 [%0], %1;"
                     :: "l"(&g_flag[cid]), "r"(1) : "memory");
    }

    // ---- phase 2a: parallel wait on predecessor flags + gather end-times ----
    if (d < k) {
        int f;
        do {
            asm volatile("ld.acquire.gpu.global.b32 %0, [%1];"
                         : "=r"(f) : "l"(&g_flag[base + d]) : "memory");
            if (!f) __nanosleep(64);
        } while (!f);
        s_T[d] = tb[(d + 1) * CS - 1];
    }
    __syncthreads();

    // ---- phase 2b: closed-form carry, 4 independent accumulators ----
    float c0 = 0.f, c1 = 0.f, c2 = 0.f, c3 = 0.f;
    const float* Lp = g_L + (size_t)base * D + d;
    int j = 0;
    for (; j + 4 <= k; j += 4) {
        c0 = fmaf(__expf(-THETA * (Tprev - s_T[j + 0])), Lp[(size_t)(j + 0) * D], c0);
        c1 = fmaf(__expf(-THETA * (Tprev - s_T[j + 1])), Lp[(size_t)(j + 1) * D], c1);
        c2 = fmaf(__expf(-THETA * (Tprev - s_T[j + 2])), Lp[(size_t)(j + 2) * D], c2);
        c3 = fmaf(__expf(-THETA * (Tprev - s_T[j + 3])), Lp[(size_t)(j + 3) * D], c3);
    }
    for (; j < k; ++j)
        c0 = fmaf(__expf(-THETA * (Tprev - s_T[j])), Lp[(size_t)j * D], c0);
    const float carry = (c0 + c1) + (c2 + c3);

    // ---- phase 3: apply carry, stream results out ----
    float* ob = out + ((size_t)b * S + s0) * D + d;
    #pragma unroll 8
    for (int s2 = 0; s2 < rows; ++s2) {
        float v = fmaf(s_e[s2], carry, s_buf[s2 * D + d]);
        __stcs(ob + (size_t)s2 * D, v);
    }
}

extern "C" void kernel_launch(void* const* d_in, const int* in_sizes, int n_in,
                              void* d_out, int out_size)
{
    const float* t  = (const float*)d_in[0];   // [B,S,1]
    const float* x0 = (const float*)d_in[1];   // [B,1,D]
    const float* z  = (const float*)d_in[2];   // [B,S,D]
    float* out = (float*)d_out;                // [B,S,D]

    const long n_t  = in_sizes[0];
    const long n_x0 = in_sizes[1];
    const long n_z  = in_sizes[2];
    const int D = (int)(n_z / n_t);
    const int B = (int)(n_x0 / D);
    const int S = (int)(n_t / B);
    const int chunks = (S + CS - 1) / CS;

    const int nflags = B * chunks;
    init_flags_kernel<<<(nflags + 255) / 256, 256>>>(nflags);

    const size_t smem = (size_t)(3 * CS + chunks + CS * D) * sizeof(float);
    cudaFuncSetAttribute(ou_scan_kernel,
                         cudaFuncAttributeMaxDynamicSharedMemorySize, (int)smem);
    ou_scan_kernel<<<B * chunks, D, smem>>>(t, x0, z, out, B, S, D, chunks);
}

// round 5
// speedup vs baseline: 4.6769x; 1.1257x over previous
#include <cuda_runtime.h>

#define THETA 0.5f
#define CS 64            // rows per chunk (per block)
#define NG 4             // row subgroups per block
#define RG (CS / NG)     // rows per subgroup (16)
#define PF 4             // prefetch depth in float4 rows
#define SM_HDR 264       // float offset of float4 region (multiple of 4 => 16B aligned)

// Scratch: per-chunk local endpoints + ready flags.
__device__ float g_L[1 << 21];   // B*chunks*D = 64*64*256 floats max
__device__ int   g_flag[16384];

__global__ void init_flags_kernel(int n) {
    int i = blockIdx.x * blockDim.x + threadIdx.x;
    if (i < n) g_flag[i] = 0;
}

__global__ __launch_bounds__(256, 3)
void ou_scan_kernel(const float* __restrict__ t,
                    const float* __restrict__ x0,
                    const float* __restrict__ z,
                    float* __restrict__ out,
                    int B, int S, int D, int chunks)
{
    extern __shared__ __align__(16) float sm[];
    float*  s_c  = sm;                  // [CS]  per-row decay
    float*  s_r  = sm + CS;             // [CS]  per-row noise scale
    float*  s_e  = sm + 2 * CS;         // [CS]  per-row weight rel. to OWN group start
    float*  s_T  = sm + 3 * CS;         // [64]  predecessor chunk end-times
    float*  s_Tg = sm + 3 * CS + 64;    // [NG]  subgroup end-times
    float4* s_Lg = (float4*)(sm + SM_HDR);          // [NG * 64] subgroup endpoints
    float4* s_buf= s_Lg + NG * 64;                  // [CS * 64] local scan results

    const int b  = blockIdx.x / chunks;
    const int k  = blockIdx.x % chunks;
    const int s0 = k * CS;
    const int tid = threadIdx.x;
    const int g  = tid >> 6;            // subgroup 0..3
    const int l  = tid & 63;            // float4 lane (d = 4*l)

    const float* tb = t + (size_t)b * S;
    const float Tprev = (k == 0) ? 0.0f : tb[s0 - 1];

    // ---- phase 0: per-row constants ----
    if (tid < CS) {
        const int i = tid;
        float tc = tb[s0 + i];
        float tp = (s0 + i == 0) ? 0.0f : tb[s0 + i - 1];
        float c  = __expf(-THETA * (tc - tp));
        s_c[i] = c;
        s_r[i] = sqrtf(fmaxf(1.0f - c * c, 0.0f));
        // weight relative to this row's OWN subgroup start
        float tbase = (i < RG) ? Tprev : tb[s0 + (i / RG) * RG - 1];
        s_e[i] = __expf(-THETA * (tc - tbase));
    }
    if (tid < NG) s_Tg[tid] = tb[s0 + (tid + 1) * RG - 1];
    __syncthreads();

    // ---- phase 1: subgroup-local scan, float4, depth-2 pipeline ----
    const int r0 = g * RG;
    const float4* zb4 = (const float4*)(z + ((size_t)b * S + s0 + r0) * D) + l;
    const int strd = D >> 2;            // 64 float4 per row

    float4 x = make_float4(0.f, 0.f, 0.f, 0.f);
    if (k == 0 && g == 0) x = ((const float4*)(x0 + (size_t)b * D))[l];

    float4 cur[PF], nxt[PF];
    #pragma unroll
    for (int u = 0; u < PF; ++u) cur[u] = __ldcs(zb4 + (size_t)u * strd);
    for (int s = 0; s < RG; s += PF) {
        if (s + 2 * PF <= RG) {
            #pragma unroll
            for (int u = 0; u < PF; ++u)
                nxt[u] = __ldcs(zb4 + (size_t)(s + PF + u) * strd);
        }
        #pragma unroll
        for (int u = 0; u < PF; ++u) {
            const float c = s_c[r0 + s + u];
            const float r = s_r[r0 + s + u];
            x.x = fmaf(c, x.x, r * cur[u].x);
            x.y = fmaf(c, x.y, r * cur[u].y);
            x.z = fmaf(c, x.z, r * cur[u].z);
            x.w = fmaf(c, x.w, r * cur[u].w);
            s_buf[(r0 + s + u) * 64 + l] = x;
        }
        #pragma unroll
        for (int u = 0; u < PF; ++u) cur[u] = nxt[u];
    }
    s_Lg[g * 64 + l] = x;               // subgroup-local endpoint
    __syncthreads();

    // ---- publish block endpoint (combined across subgroups), release flag ----
    const int base = b * chunks;
    const int cid  = base + k;
    if (g == NG - 1) {
        const float Tend = s_Tg[NG - 1];
        float4 Lb = x;                  // own subgroup-3 endpoint
        #pragma unroll
        for (int gp = 0; gp < NG - 1; ++gp) {
            const float w = __expf(-THETA * (Tend - s_Tg[gp]));
            const float4 Lg = s_Lg[gp * 64 + l];
            Lb.x = fmaf(w, Lg.x, Lb.x);
            Lb.y = fmaf(w, Lg.y, Lb.y);
            Lb.z = fmaf(w, Lg.z, Lb.z);
            Lb.w = fmaf(w, Lg.w, Lb.w);
        }
        ((float4*)g_L)[(size_t)cid * 64 + l] = Lb;
    }
    __threadfence();
    __syncthreads();
    if (tid == 0) {
        asm volatile("st.release.gpu.global.b32 [%0], %1;"
                     :: "l"(&g_flag[cid]), "r"(1) : "memory");
    }

    // ---- phase 2a: parallel wait on predecessor flags + gather end-times ----
    if (tid < k) {
        int f;
        do {
            asm volatile("ld.acquire.gpu.global.b32 %0, [%1];"
                         : "=r"(f) : "l"(&g_flag[base + tid]) : "memory");
            if (!f) __nanosleep(64);
        } while (!f);
        s_T[tid] = tb[(tid + 1) * CS - 1];
    }
    __syncthreads();

    // ---- phase 2b: block carry (closed form over predecessor chunks) ----
    float4 a0 = make_float4(0.f, 0.f, 0.f, 0.f);
    float4 a1 = make_float4(0.f, 0.f, 0.f, 0.f);
    const float4* Lp = ((const float4*)g_L) + (size_t)base * 64 + l;
    int j = 0;
    for (; j + 2 <= k; j += 2) {
        const float w0 = __expf(-THETA * (Tprev - s_T[j]));
        const float w1 = __expf(-THETA * (Tprev - s_T[j + 1]));
        const float4 L0 = Lp[(size_t)j * 64];
        const float4 L1 = Lp[(size_t)(j + 1) * 64];
        a0.x = fmaf(w0, L0.x, a0.x); a0.y = fmaf(w0, L0.y, a0.y);
        a0.z = fmaf(w0, L0.z, a0.z); a0.w = fmaf(w0, L0.w, a0.w);
        a1.x = fmaf(w1, L1.x, a1.x); a1.y = fmaf(w1, L1.y, a1.y);
        a1.z = fmaf(w1, L1.z, a1.z); a1.w = fmaf(w1, L1.w, a1.w);
    }
    if (j < k) {
        const float w0 = __expf(-THETA * (Tprev - s_T[j]));
        const float4 L0 = Lp[(size_t)j * 64];
        a0.x = fmaf(w0, L0.x, a0.x); a0.y = fmaf(w0, L0.y, a0.y);
        a0.z = fmaf(w0, L0.z, a0.z); a0.w = fmaf(w0, L0.w, a0.w);
    }
    float4 carry = make_float4(a0.x + a1.x, a0.y + a1.y, a0.z + a1.z, a0.w + a1.w);

    // ---- state entering THIS thread's subgroup ----
    const float Tgprev = (g == 0) ? Tprev : s_Tg[g - 1];
    {
        const float wb = __expf(-THETA * (Tgprev - Tprev));   // 1.0 for g==0
        carry.x *= wb; carry.y *= wb; carry.z *= wb; carry.w *= wb;
        for (int gp = 0; gp < g; ++gp) {
            const float w = __expf(-THETA * (Tgprev - s_Tg[gp]));
            const float4 Lg = s_Lg[gp * 64 + l];
            carry.x = fmaf(w, Lg.x, carry.x);
            carry.y = fmaf(w, Lg.y, carry.y);
            carry.z = fmaf(w, Lg.z, carry.z);
            carry.w = fmaf(w, Lg.w, carry.w);
        }
    }

    // ---- phase 3: apply carry, stream results out (float4) ----
    float4* ob4 = (float4*)(out + ((size_t)b * S + s0 + r0) * D) + l;
    #pragma unroll 4
    for (int s = 0; s < RG; ++s) {
        const float e = s_e[r0 + s];
        float4 v = s_buf[(r0 + s) * 64 + l];
        v.x = fmaf(e, carry.x, v.x);
        v.y = fmaf(e, carry.y, v.y);
        v.z = fmaf(e, carry.z, v.z);
        v.w = fmaf(e, carry.w, v.w);
        __stcs(ob4 + (size_t)s * strd, v);
    }
}

extern "C" void kernel_launch(void* const* d_in, const int* in_sizes, int n_in,
                              void* d_out, int out_size)
{
    const float* t  = (const float*)d_in[0];   // [B,S,1]
    const float* x0 = (const float*)d_in[1];   // [B,1,D]
    const float* z  = (const float*)d_in[2];   // [B,S,D]
    float* out = (float*)d_out;                // [B,S,D]

    const long n_t  = in_sizes[0];
    const long n_x0 = in_sizes[1];
    const long n_z  = in_sizes[2];
    const int D = (int)(n_z / n_t);
    const int B = (int)(n_x0 / D);
    const int S = (int)(n_t / B);
    const int chunks = (S + CS - 1) / CS;

    const int nflags = B * chunks;
    init_flags_kernel<<<(nflags + 255) / 256, 256>>>(nflags);

    // smem: SM_HDR floats header (16B aligned), then NG*64 + CS*64 float4
    const size_t smem = SM_HDR * sizeof(float)
                      + (size_t)(NG * 64 + CS * 64) * sizeof(float4);
    cudaFuncSetAttribute(ou_scan_kernel,
                         cudaFuncAttributeMaxDynamicSharedMemorySize, (int)smem);
    ou_scan_kernel<<<B * chunks, 256, smem>>>(t, x0, z, out, B, S, D, chunks);
}

// round 6
// speedup vs baseline: 5.6228x; 1.2022x over previous
#include <cuda_runtime.h>

#define THETA 0.5f
#define CS 64            // rows per chunk (per block)
#define NG 4             // row subgroups per block
#define RG (CS / NG)     // rows per subgroup (16)
#define PF 4             // prefetch depth in float4 rows
#define SM_HDR 200       // float offset of float4 region (16B aligned: 200*4=800)

// Scratch: per-chunk local endpoints + ready flags.
__device__ float g_L[1 << 21];   // B*chunks*D floats max
__device__ int   g_flag[16384];

__global__ void init_flags_kernel(int n) {
    int i = blockIdx.x * blockDim.x + threadIdx.x;
    if (i < n) g_flag[i] = 0;
}

__global__ __launch_bounds__(256, 4)
void ou_scan_kernel(const float* __restrict__ t,
                    const float* __restrict__ x0,
                    const float* __restrict__ z,
                    float* __restrict__ out,
                    int B, int S, int D, int chunks)
{
    extern __shared__ __align__(16) float sm[];
    float*  s_c  = sm;                  // [CS] per-row decay
    float*  s_r  = sm + CS;             // [CS] per-row noise scale
    float*  s_T  = sm + 2 * CS;         // [64] predecessor chunk end-times
    float*  s_Tg = sm + 2 * CS + 64;    // [NG] subgroup end-times
    float4* s_Lg = (float4*)(sm + SM_HDR);   // [NG * 64] subgroup endpoints

    const int b  = blockIdx.x / chunks;
    const int k  = blockIdx.x % chunks;
    const int s0 = k * CS;
    const int rows = min(CS, S - s0);
    const bool full = (rows == CS);
    const int tid = threadIdx.x;
    const int g  = tid >> 6;            // subgroup 0..3
    const int l  = tid & 63;            // float4 lane (d = 4*l)

    const float* tb = t + (size_t)b * S;
    const float Tprev = (k == 0) ? 0.0f : tb[s0 - 1];

    // ---- phase 0: per-row constants ----
    if (tid < rows) {
        const int i = tid;
        float tc = tb[s0 + i];
        float tp = (s0 + i == 0) ? 0.0f : tb[s0 + i - 1];
        float c  = __expf(-THETA * (tc - tp));
        s_c[i] = c;
        s_r[i] = sqrtf(fmaxf(1.0f - c * c, 0.0f));
    }
    if (tid < NG) s_Tg[tid] = tb[min(s0 + (tid + 1) * RG - 1, S - 1)];
    __syncthreads();

    // ---- phase 1: subgroup-local endpoint only (default caching -> L2) ----
    const int r0 = g * RG;
    const float4* zb4 = (const float4*)(z + ((size_t)b * S + s0 + r0) * D) + l;
    const int strd = D >> 2;            // float4 per row

    float4 x = make_float4(0.f, 0.f, 0.f, 0.f);
    if (k == 0 && g == 0) x = ((const float4*)(x0 + (size_t)b * D))[l];

    if (full) {
        float4 cur[PF], nxt[PF];
        #pragma unroll
        for (int u = 0; u < PF; ++u) cur[u] = zb4[(size_t)u * strd];
        for (int s = 0; s < RG; s += PF) {
            if (s + 2 * PF <= RG) {
                #pragma unroll
                for (int u = 0; u < PF; ++u)
                    nxt[u] = zb4[(size_t)(s + PF + u) * strd];
            }
            #pragma unroll
            for (int u = 0; u < PF; ++u) {
                const float c = s_c[r0 + s + u];
                const float r = s_r[r0 + s + u];
                x.x = fmaf(c, x.x, r * cur[u].x);
                x.y = fmaf(c, x.y, r * cur[u].y);
                x.z = fmaf(c, x.z, r * cur[u].z);
                x.w = fmaf(c, x.w, r * cur[u].w);
            }
            #pragma unroll
            for (int u = 0; u < PF; ++u) cur[u] = nxt[u];
        }
    } else {
        const int gr = max(0, min(RG, rows - r0));
        for (int s = 0; s < gr; ++s) {
            const float4 zv = zb4[(size_t)s * strd];
            const float c = s_c[r0 + s], r = s_r[r0 + s];
            x.x = fmaf(c, x.x, r * zv.x);
            x.y = fmaf(c, x.y, r * zv.y);
            x.z = fmaf(c, x.z, r * zv.z);
            x.w = fmaf(c, x.w, r * zv.w);
        }
    }
    s_Lg[g * 64 + l] = x;
    __syncthreads();

    // ---- publish block endpoint (combined across subgroups), release flag ----
    const int base = b * chunks;
    const int cid  = base + k;
    if (g == NG - 1) {
        const float Tend = s_Tg[NG - 1];
        float4 Lb = x;
        #pragma unroll
        for (int gp = 0; gp < NG - 1; ++gp) {
            const float w = __expf(-THETA * (Tend - s_Tg[gp]));
            const float4 Lg = s_Lg[gp * 64 + l];
            Lb.x = fmaf(w, Lg.x, Lb.x);
            Lb.y = fmaf(w, Lg.y, Lb.y);
            Lb.z = fmaf(w, Lg.z, Lb.z);
            Lb.w = fmaf(w, Lg.w, Lb.w);
        }
        ((float4*)g_L)[(size_t)cid * 64 + l] = Lb;
    }
    __threadfence();
    __syncthreads();
    if (tid == 0) {
        asm volatile("st.release.gpu.global.b32 [%0], %1;"
                     :: "l"(&g_flag[cid]), "r"(1) : "memory");
    }

    // ---- phase 2a: parallel wait on predecessor flags + gather end-times ----
    if (tid < k) {
        int f;
        do {
            asm volatile("ld.acquire.gpu.global.b32 %0, [%1];"
                         : "=r"(f) : "l"(&g_flag[base + tid]) : "memory");
            if (!f) __nanosleep(64);
        } while (!f);
        s_T[tid] = tb[(tid + 1) * CS - 1];
    }
    __syncthreads();

    // ---- phase 2b: block carry (closed form over predecessor chunks) ----
    float4 a0 = make_float4(0.f, 0.f, 0.f, 0.f);
    float4 a1 = make_float4(0.f, 0.f, 0.f, 0.f);
    const float4* Lp = ((const float4*)g_L) + (size_t)base * 64 + l;
    int j = 0;
    for (; j + 2 <= k; j += 2) {
        const float w0 = __expf(-THETA * (Tprev - s_T[j]));
        const float w1 = __expf(-THETA * (Tprev - s_T[j + 1]));
        const float4 L0 = Lp[(size_t)j * 64];
        const float4 L1 = Lp[(size_t)(j + 1) * 64];
        a0.x = fmaf(w0, L0.x, a0.x); a0.y = fmaf(w0, L0.y, a0.y);
        a0.z = fmaf(w0, L0.z, a0.z); a0.w = fmaf(w0, L0.w, a0.w);
        a1.x = fmaf(w1, L1.x, a1.x); a1.y = fmaf(w1, L1.y, a1.y);
        a1.z = fmaf(w1, L1.z, a1.z); a1.w = fmaf(w1, L1.w, a1.w);
    }
    if (j < k) {
        const float w0 = __expf(-THETA * (Tprev - s_T[j]));
        const float4 L0 = Lp[(size_t)j * 64];
        a0.x = fmaf(w0, L0.x, a0.x); a0.y = fmaf(w0, L0.y, a0.y);
        a0.z = fmaf(w0, L0.z, a0.z); a0.w = fmaf(w0, L0.w, a0.w);
    }
    float4 carry = make_float4(a0.x + a1.x, a0.y + a1.y, a0.z + a1.z, a0.w + a1.w);

    // ---- state entering THIS thread's subgroup ----
    const float Tgprev = (g == 0) ? Tprev : s_Tg[g - 1];
    {
        const float wb = __expf(-THETA * (Tgprev - Tprev));   // 1.0 for g==0
        carry.x *= wb; carry.y *= wb; carry.z *= wb; carry.w *= wb;
        for (int gp = 0; gp < g; ++gp) {
            const float w = __expf(-THETA * (Tgprev - s_Tg[gp]));
            const float4 Lg = s_Lg[gp * 64 + l];
            carry.x = fmaf(w, Lg.x, carry.x);
            carry.y = fmaf(w, Lg.y, carry.y);
            carry.z = fmaf(w, Lg.z, carry.z);
            carry.w = fmaf(w, Lg.w, carry.w);
        }
    }
    if (k == 0 && g == 0) {   // seed with x0 (carry is 0 here)
        const float4 xv = ((const float4*)(x0 + (size_t)b * D))[l];
        carry.x += xv.x; carry.y += xv.y; carry.z += xv.z; carry.w += xv.w;
    }

    // ---- phase 3: re-read z (L2-resident), recompute with true carry ----
    float4* ob4 = (float4*)(out + ((size_t)b * S + s0 + r0) * D) + l;
    float4 y = carry;
    if (full) {
        float4 cur[PF], nxt[PF];
        #pragma unroll
        for (int u = 0; u < PF; ++u) cur[u] = __ldcs(zb4 + (size_t)u * strd);
        for (int s = 0; s < RG; s += PF) {
            if (s + 2 * PF <= RG) {
                #pragma unroll
                for (int u = 0; u < PF; ++u)
                    nxt[u] = __ldcs(zb4 + (size_t)(s + PF + u) * strd);
            }
            #pragma unroll
            for (int u = 0; u < PF; ++u) {
                const float c = s_c[r0 + s + u];
                const float r = s_r[r0 + s + u];
                y.x = fmaf(c, y.x, r * cur[u].x);
                y.y = fmaf(c, y.y, r * cur[u].y);
                y.z = fmaf(c, y.z, r * cur[u].z);
                y.w = fmaf(c, y.w, r * cur[u].w);
                __stcs(ob4 + (size_t)(s + u) * strd, y);
            }
            #pragma unroll
            for (int u = 0; u < PF; ++u) cur[u] = nxt[u];
        }
    } else {
        const int gr = max(0, min(RG, rows - r0));
        for (int s = 0; s < gr; ++s) {
            const float4 zv = __ldcs(zb4 + (size_t)s * strd);
            const float c = s_c[r0 + s], r = s_r[r0 + s];
            y.x = fmaf(c, y.x, r * zv.x);
            y.y = fmaf(c, y.y, r * zv.y);
            y.z = fmaf(c, y.z, r * zv.z);
            y.w = fmaf(c, y.w, r * zv.w);
            __stcs(ob4 + (size_t)s * strd, y);
        }
    }
}

extern "C" void kernel_launch(void* const* d_in, const int* in_sizes, int n_in,
                              void* d_out, int out_size)
{
    const float* t  = (const float*)d_in[0];   // [B,S,1]
    const float* x0 = (const float*)d_in[1];   // [B,1,D]
    const float* z  = (const float*)d_in[2];   // [B,S,D]
    float* out = (float*)d_out;                // [B,S,D]

    const long n_t  = in_sizes[0];
    const long n_x0 = in_sizes[1];
    const long n_z  = in_sizes[2];
    const int D = (int)(n_z / n_t);
    const int B = (int)(n_x0 / D);
    const int S = (int)(n_t / B);
    const int chunks = (S + CS - 1) / CS;

    const int nflags = B * chunks;
    init_flags_kernel<<<(nflags + 255) / 256, 256>>>(nflags);

    const size_t smem = SM_HDR * sizeof(float) + (size_t)(NG * 64) * sizeof(float4);
    cudaFuncSetAttribute(ou_scan_kernel,
                         cudaFuncAttributeMaxDynamicSharedMemorySize, (int)smem);
    ou_scan_kernel<<<B * chunks, 256, smem>>>(t, x0, z, out, B, S, D, chunks);
}

// round 7
// speedup vs baseline: 6.4637x; 1.1496x over previous
#include <cuda_runtime.h>

#define THETA 0.5f
#define CS 128           // rows per chunk (per block)
#define NG 4             // row subgroups per block
#define RG (CS / NG)     // rows per subgroup (32)
#define PF 4             // prefetch depth in float4 rows
#define SM_HDR 328       // float offset of float4 region (328*4=1312, 16B aligned)

// Scratch: per-chunk local endpoints + ready flags.
__device__ float g_L[1 << 21];   // B*chunks*D floats max
__device__ int   g_flag[16384];

__global__ void init_flags_kernel(int n) {
    int i = blockIdx.x * blockDim.x + threadIdx.x;
    if (i < n) g_flag[i] = 0;
}

__global__ __launch_bounds__(256, 4)
void ou_scan_kernel(const float* __restrict__ t,
                    const float* __restrict__ x0,
                    const float* __restrict__ z,
                    float* __restrict__ out,
                    int B, int S, int D, int chunks)
{
    extern __shared__ __align__(16) float sm[];
    float*  s_c  = sm;                  // [CS]  per-row decay
    float*  s_r  = sm + CS;             // [CS]  per-row noise scale
    float*  s_T  = sm + 2 * CS;         // [64]  predecessor chunk end-times
    float*  s_Tg = sm + 2 * CS + 64;    // [NG]  subgroup end-times
    float4* s_Lg = (float4*)(sm + SM_HDR);   // [NG * 64] subgroup endpoints

    const int b  = blockIdx.x / chunks;
    const int k  = blockIdx.x % chunks;
    const int s0 = k * CS;
    const int rows = min(CS, S - s0);
    const bool full = (rows == CS);
    const int tid = threadIdx.x;
    const int g  = tid >> 6;            // subgroup 0..3
    const int l  = tid & 63;            // float4 lane (d = 4*l)

    const float* tb = t + (size_t)b * S;
    const float Tprev = (k == 0) ? 0.0f : tb[s0 - 1];

    // ---- phase 0: per-row constants ----
    for (int i = tid; i < rows; i += 256) {
        float tc = tb[s0 + i];
        float tp = (s0 + i == 0) ? 0.0f : tb[s0 + i - 1];
        float c  = __expf(-THETA * (tc - tp));
        s_c[i] = c;
        s_r[i] = sqrtf(fmaxf(1.0f - c * c, 0.0f));
    }
    if (tid < NG) s_Tg[tid] = tb[min(s0 + (tid + 1) * RG - 1, S - 1)];
    __syncthreads();

    // ---- phase 1: subgroup-local endpoint only (default caching -> L2) ----
    const int r0 = g * RG;
    const float4* zb4 = (const float4*)(z + ((size_t)b * S + s0 + r0) * D) + l;
    const int strd = D >> 2;            // float4 per row

    float4 x = make_float4(0.f, 0.f, 0.f, 0.f);
    if (k == 0 && g == 0) x = ((const float4*)(x0 + (size_t)b * D))[l];

    if (full) {
        float4 cur[PF], nxt[PF];
        #pragma unroll
        for (int u = 0; u < PF; ++u) cur[u] = zb4[(size_t)u * strd];
        for (int s = 0; s < RG; s += PF) {
            if (s + 2 * PF <= RG) {
                #pragma unroll
                for (int u = 0; u < PF; ++u)
                    nxt[u] = zb4[(size_t)(s + PF + u) * strd];
            }
            #pragma unroll
            for (int u = 0; u < PF; ++u) {
                const float c = s_c[r0 + s + u];
                const float r = s_r[r0 + s + u];
                x.x = fmaf(c, x.x, r * cur[u].x);
                x.y = fmaf(c, x.y, r * cur[u].y);
                x.z = fmaf(c, x.z, r * cur[u].z);
                x.w = fmaf(c, x.w, r * cur[u].w);
            }
            #pragma unroll
            for (int u = 0; u < PF; ++u) cur[u] = nxt[u];
        }
    } else {
        const int gr = max(0, min(RG, rows - r0));
        for (int s = 0; s < gr; ++s) {
            const float4 zv = zb4[(size_t)s * strd];
            const float c = s_c[r0 + s], r = s_r[r0 + s];
            x.x = fmaf(c, x.x, r * zv.x);
            x.y = fmaf(c, x.y, r * zv.y);
            x.z = fmaf(c, x.z, r * zv.z);
            x.w = fmaf(c, x.w, r * zv.w);
        }
    }
    s_Lg[g * 64 + l] = x;
    __syncthreads();

    // ---- publish block endpoint (combined across subgroups), release flag ----
    const int base = b * chunks;
    const int cid  = base + k;
    if (g == NG - 1) {
        const float Tend = s_Tg[NG - 1];
        float4 Lb = x;
        #pragma unroll
        for (int gp = 0; gp < NG - 1; ++gp) {
            const float w = __expf(-THETA * (Tend - s_Tg[gp]));
            const float4 Lg = s_Lg[gp * 64 + l];
            Lb.x = fmaf(w, Lg.x, Lb.x);
            Lb.y = fmaf(w, Lg.y, Lb.y);
            Lb.z = fmaf(w, Lg.z, Lb.z);
            Lb.w = fmaf(w, Lg.w, Lb.w);
        }
        ((float4*)g_L)[(size_t)cid * 64 + l] = Lb;
    }
    __syncthreads();
    if (tid == 0) {
        asm volatile("st.release.gpu.global.b32 [%0], %1;"
                     :: "l"(&g_flag[cid]), "r"(1) : "memory");
    }

    // ---- phase 2a: parallel wait on predecessor flags + gather end-times ----
    if (tid < k) {
        int f;
        do {
            asm volatile("ld.acquire.gpu.global.b32 %0, [%1];"
                         : "=r"(f) : "l"(&g_flag[base + tid]) : "memory");
            if (!f) __nanosleep(64);
        } while (!f);
        s_T[tid] = tb[(tid + 1) * CS - 1];
    }
    __syncthreads();

    // ---- phase 2b: block carry (closed form over predecessor chunks) ----
    float4 a0 = make_float4(0.f, 0.f, 0.f, 0.f);
    float4 a1 = make_float4(0.f, 0.f, 0.f, 0.f);
    const float4* Lp = ((const float4*)g_L) + (size_t)base * 64 + l;
    int j = 0;
    for (; j + 2 <= k; j += 2) {
        const float w0 = __expf(-THETA * (Tprev - s_T[j]));
        const float w1 = __expf(-THETA * (Tprev - s_T[j + 1]));
        const float4 L0 = Lp[(size_t)j * 64];
        const float4 L1 = Lp[(size_t)(j + 1) * 64];
        a0.x = fmaf(w0, L0.x, a0.x); a0.y = fmaf(w0, L0.y, a0.y);
        a0.z = fmaf(w0, L0.z, a0.z); a0.w = fmaf(w0, L0.w, a0.w);
        a1.x = fmaf(w1, L1.x, a1.x); a1.y = fmaf(w1, L1.y, a1.y);
        a1.z = fmaf(w1, L1.z, a1.z); a1.w = fmaf(w1, L1.w, a1.w);
    }
    if (j < k) {
        const float w0 = __expf(-THETA * (Tprev - s_T[j]));
        const float4 L0 = Lp[(size_t)j * 64];
        a0.x = fmaf(w0, L0.x, a0.x); a0.y = fmaf(w0, L0.y, a0.y);
        a0.z = fmaf(w0, L0.z, a0.z); a0.w = fmaf(w0, L0.w, a0.w);
    }
    float4 carry = make_float4(a0.x + a1.x, a0.y + a1.y, a0.z + a1.z, a0.w + a1.w);

    // ---- state entering THIS thread's subgroup ----
    const float Tgprev = (g == 0) ? Tprev : s_Tg[g - 1];
    {
        const float wb = __expf(-THETA * (Tgprev - Tprev));   // 1.0 for g==0
        carry.x *= wb; carry.y *= wb; carry.z *= wb; carry.w *= wb;
        for (int gp = 0; gp < g; ++gp) {
            const float w = __expf(-THETA * (Tgprev - s_Tg[gp]));
            const float4 Lg = s_Lg[gp * 64 + l];
            carry.x = fmaf(w, Lg.x, carry.x);
            carry.y = fmaf(w, Lg.y, carry.y);
            carry.z = fmaf(w, Lg.z, carry.z);
            carry.w = fmaf(w, Lg.w, carry.w);
        }
    }
    if (k == 0 && g == 0) {   // seed with x0 (carry is 0 here)
        const float4 xv = ((const float4*)(x0 + (size_t)b * D))[l];
        carry.x += xv.x; carry.y += xv.y; carry.z += xv.z; carry.w += xv.w;
    }

    // ---- phase 3: re-read z (L2-resident), recompute with true carry ----
    float4* ob4 = (float4*)(out + ((size_t)b * S + s0 + r0) * D) + l;
    float4 y = carry;
    if (full) {
        float4 cur[PF], nxt[PF];
        #pragma unroll
        for (int u = 0; u < PF; ++u) cur[u] = __ldcs(zb4 + (size_t)u * strd);
        for (int s = 0; s < RG; s += PF) {
            if (s + 2 * PF <= RG) {
                #pragma unroll
                for (int u = 0; u < PF; ++u)
                    nxt[u] = __ldcs(zb4 + (size_t)(s + PF + u) * strd);
            }
            #pragma unroll
            for (int u = 0; u < PF; ++u) {
                const float c = s_c[r0 + s + u];
                const float r = s_r[r0 + s + u];
                y.x = fmaf(c, y.x, r * cur[u].x);
                y.y = fmaf(c, y.y, r * cur[u].y);
                y.z = fmaf(c, y.z, r * cur[u].z);
                y.w = fmaf(c, y.w, r * cur[u].w);
                __stcs(ob4 + (size_t)(s + u) * strd, y);
            }
            #pragma unroll
            for (int u = 0; u < PF; ++u) cur[u] = nxt[u];
        }
    } else {
        const int gr = max(0, min(RG, rows - r0));
        for (int s = 0; s < gr; ++s) {
            const float4 zv = __ldcs(zb4 + (size_t)s * strd);
            const float c = s_c[r0 + s], r = s_r[r0 + s];
            y.x = fmaf(c, y.x, r * zv.x);
            y.y = fmaf(c, y.y, r * zv.y);
            y.z = fmaf(c, y.z, r * zv.z);
            y.w = fmaf(c, y.w, r * zv.w);
            __stcs(ob4 + (size_t)s * strd, y);
        }
    }
}

extern "C" void kernel_launch(void* const* d_in, const int* in_sizes, int n_in,
                              void* d_out, int out_size)
{
    const float* t  = (const float*)d_in[0];   // [B,S,1]
    const float* x0 = (const float*)d_in[1];   // [B,1,D]
    const float* z  = (const float*)d_in[2];   // [B,S,D]
    float* out = (float*)d_out;                // [B,S,D]

    const long n_t  = in_sizes[0];
    const long n_x0 = in_sizes[1];
    const long n_z  = in_sizes[2];
    const int D = (int)(n_z / n_t);
    const int B = (int)(n_x0 / D);
    const int S = (int)(n_t / B);
    const int chunks = (S + CS - 1) / CS;

    const int nflags = B * chunks;
    init_flags_kernel<<<(nflags + 255) / 256, 256>>>(nflags);

    const size_t smem = SM_HDR * sizeof(float) + (size_t)(NG * 64) * sizeof(float4);
    cudaFuncSetAttribute(ou_scan_kernel,
                         cudaFuncAttributeMaxDynamicSharedMemorySize, (int)smem);
    ou_scan_kernel<<<B * chunks, 256, smem>>>(t, x0, z, out, B, S, D, chunks);
}